// round 11
// baseline (speedup 1.0000x reference)
#include <cuda_runtime.h>
#include <cuda_bf16.h>
#include <cstdint>

// ---------------------------------------------------------------------------
// Problem constants
// ---------------------------------------------------------------------------
#define DIM   128
#define B_FIX 256
#define N_FIX 131072
#define TN    64                  // y-rows per subtile
#define SUBT  (N_FIX / TN)        // 2048
#define NSC   148                 // subtile streams (one per SM)
#define GRIDX (NSC * 2)           // 296 CTAs: 2 per SM, row-split
#define NC    (NSC * 2 * 4)       // 1184 packed candidates per row
#define NSEL  12                  // columns rescored exactly
#define KK    8
#define NEGF  -3.0e38f

// ---------------------------------------------------------------------------
// Global scratch (static)
// ---------------------------------------------------------------------------
__device__ uint32_t g_cpack[(size_t)B_FIX * NC];   // key15<<17 | column17
__device__ int      g_pos[B_FIX];

// SMEM layout for gemm kernel (bytes)
#define XS_OFF   0
#define XS_SIZE  (128 * 256)                 // 128 rows x 256B (bf16 swizzled)
#define YS_OFF   XS_SIZE                     // 32768
#define YS_SIZE  (64 * 256)                  // 16384 per buffer
#define SMEM_TOTAL (YS_OFF + 2 * YS_SIZE)    // 65536  -> 2 CTAs/SM

// ---------------------------------------------------------------------------
// Helpers
// ---------------------------------------------------------------------------
__device__ __forceinline__ uint32_t smem_u32(const void* p) {
    uint32_t a;
    asm("{ .reg .u64 t; cvta.to.shared.u64 t, %1; cvt.u32.u64 %0, t; }"
        : "=r"(a) : "l"(p));
    return a;
}

__device__ __forceinline__ void ldsm_x4(uint32_t* r, uint32_t addr) {
    asm volatile("ldmatrix.sync.aligned.m8n8.x4.shared.b16 {%0,%1,%2,%3}, [%4];"
                 : "=r"(r[0]), "=r"(r[1]), "=r"(r[2]), "=r"(r[3]) : "r"(addr));
}

__device__ __forceinline__ void mma_bf16(float* d, const uint32_t* a,
                                         uint32_t b0, uint32_t b1) {
    asm volatile(
        "mma.sync.aligned.m16n8k16.row.col.f32.bf16.bf16.f32 "
        "{%0,%1,%2,%3}, {%4,%5,%6,%7}, {%8,%9}, {%0,%1,%2,%3};"
        : "+f"(d[0]), "+f"(d[1]), "+f"(d[2]), "+f"(d[3])
        : "r"(a[0]), "r"(a[1]), "r"(a[2]), "r"(a[3]), "r"(b0), "r"(b1));
}

// monotone uint key from float bits (order-preserving, both signs)
__device__ __forceinline__ uint32_t fkey(float v) {
    uint32_t f = __float_as_uint(v);
    return f ^ (uint32_t)(((int32_t)f >> 31) | 0x80000000);
}

// branchless sorted-descending insert chains (IMNMX only)
__device__ __forceinline__ void chain4(uint32_t* L, uint32_t m) {
#pragma unroll
    for (int j = 0; j < 4; j++) {
        uint32_t mx = max(L[j], m);
        m = min(L[j], m);
        L[j] = mx;
    }
}
__device__ __forceinline__ void chain8(uint32_t* L, uint32_t m) {
#pragma unroll
    for (int j = 0; j < 8; j++) {
        uint32_t mx = max(L[j], m);
        m = min(L[j], m);
        L[j] = mx;
    }
}

// ---------------------------------------------------------------------------
// Kernel 1: persistent bf16 mma.sync GEMM + in-register column-argmax mining.
//   296 CTAs x 256 threads, 2 CTAs/SM. CTA bx owns x-row half (bx&1) and
//   subtile stream sc = bx>>1. 8 warps = 4 m-groups x 2 n-groups over 128 rows.
//   Y is read by exactly 2 CTAs; Y (64 MB) fits in L2, so DRAM reads it once.
// ---------------------------------------------------------------------------
__global__ __launch_bounds__(256, 2)
void gemm_topk_kernel(const float* __restrict__ X, const float* __restrict__ Y,
                      const void* __restrict__ pos_inds, float* __restrict__ outp,
                      int N, int B) {
    extern __shared__ char smem[];
    __shared__ int s_not64;
    const uint32_t sb = smem_u32(smem);
    const int t    = threadIdx.x;
    const int lane = t & 31;
    const int wid  = t >> 5;
    const int wm   = wid >> 1;    // m-group 0..3
    const int ng   = wid & 1;     // n-group 0..1
    const int g    = lane >> 2;   // fragment row-within-8
    const int tg   = lane & 3;    // fragment col-pair
    const int bx   = blockIdx.x;
    const int half = bx & 1;      // x-row half: 0 -> rows 0..127, 1 -> 128..255
    const int sc   = bx >> 1;     // subtile stream 0..147

    // --- prep (block 0): zero out, sniff pos_inds dtype ---
    if (bx == 0 && t == 0) { outp[0] = 0.0f; s_not64 = 0; }
    __syncthreads();
    if (bx == 0 && t < B / 2) {
        long long v = ((const long long*)pos_inds)[t];
        if (v < 0 || v >= (long long)N) atomicExch(&s_not64, 1);
    }

    // --- load X half (128x128 fp32 -> bf16) into swizzled SMEM ---
    {
        const float4* xs = (const float4*)(X + (size_t)half * 128 * DIM);
#pragma unroll
        for (int i = 0; i < 16; i++) {
            int fi = t + i * 256;
            int row = fi >> 5, c4 = fi & 31;
            float4 v = xs[fi];
            __nv_bfloat162 p0 = __float22bfloat162_rn(make_float2(v.x, v.y));
            __nv_bfloat162 p1 = __float22bfloat162_rn(make_float2(v.z, v.w));
            uint32_t off = XS_OFF + row * 256 +
                           (((c4 >> 1) ^ (row & 7)) << 4) + ((c4 & 1) << 3);
            *reinterpret_cast<uint2*>(smem + off) =
                make_uint2(*reinterpret_cast<uint32_t*>(&p0),
                           *reinterpret_cast<uint32_t*>(&p1));
        }
    }

    // --- prefetch + store first Y subtile into buffer 0 ---
    float4 pf[8];
    {
        const float4* ys = (const float4*)(Y + (size_t)sc * TN * DIM);
#pragma unroll
        for (int i = 0; i < 8; i++) pf[i] = ys[t + i * 256];
#pragma unroll
        for (int i = 0; i < 8; i++) {
            int fi = t + i * 256;
            int row = fi >> 5, c4 = fi & 31;
            __nv_bfloat162 p0 = __float22bfloat162_rn(make_float2(pf[i].x, pf[i].y));
            __nv_bfloat162 p1 = __float22bfloat162_rn(make_float2(pf[i].z, pf[i].w));
            uint32_t off = YS_OFF + row * 256 +
                           (((c4 >> 1) ^ (row & 7)) << 4) + ((c4 & 1) << 3);
            *reinterpret_cast<uint2*>(smem + off) =
                make_uint2(*reinterpret_cast<uint32_t*>(&p0),
                           *reinterpret_cast<uint32_t*>(&p1));
        }
    }
    __syncthreads();

    if (bx == 0 && t < B) {
        g_pos[t] = s_not64 ? ((const int*)pos_inds)[t]
                           : (int)((const long long*)pos_inds)[t];
    }

    // --- per-lane candidate lists: 4 rows (mt,rh), top-4 packed keys each ---
    uint32_t L[2][2][4];
#pragma unroll
    for (int mt = 0; mt < 2; mt++)
#pragma unroll
        for (int rh = 0; rh < 2; rh++)
#pragma unroll
            for (int j = 0; j < 4; j++) L[mt][rh][j] = 0;

    const int sub = lane >> 3, lr = lane & 7;
    const uint32_t colbase0 = (uint32_t)(ng * 32 + tg * 2);
    int cb = 0;
    for (int st = sc; st < SUBT; st += NSC) {
        const int stn = st + NSC;
        const bool has_next = (stn < SUBT);

        if (has_next) {
            const float4* ys = (const float4*)(Y + (size_t)stn * TN * DIM);
#pragma unroll
            for (int i = 0; i < 8; i++) pf[i] = ys[t + i * 256];
        }

        const uint32_t ysb = sb + YS_OFF + cb * YS_SIZE;
        const uint32_t colbase = (uint32_t)(st * 64) + colbase0;

        float acc[2][4][4];
#pragma unroll
        for (int mt = 0; mt < 2; mt++)
#pragma unroll
            for (int nt = 0; nt < 4; nt++)
#pragma unroll
                for (int e = 0; e < 4; e++) acc[mt][nt][e] = 0.0f;

#pragma unroll
        for (int kt = 0; kt < 8; kt++) {
            uint32_t a[2][4], b[2][4];
            {
                int rowa = wm * 32 + ((sub & 1) << 3) + lr;
                int ca   = 2 * kt + (sub >> 1);
#pragma unroll
                for (int mt = 0; mt < 2; mt++) {
                    int row = rowa + mt * 16;
                    uint32_t addr = sb + XS_OFF + row * 256 +
                                    ((ca ^ (row & 7)) << 4);
                    ldsm_x4(a[mt], addr);
                }
            }
            {
                int rowb = ng * 32 + ((sub >> 1) << 3) + lr;
                int cbk  = 2 * kt + (sub & 1);
#pragma unroll
                for (int p = 0; p < 2; p++) {
                    int row = rowb + p * 16;
                    uint32_t addr = ysb + row * 256 + ((cbk ^ (row & 7)) << 4);
                    ldsm_x4(b[p], addr);
                }
            }
#pragma unroll
            for (int mt = 0; mt < 2; mt++)
#pragma unroll
                for (int nt = 0; nt < 4; nt++)
                    mma_bf16(acc[mt][nt], a[mt],
                             b[nt >> 1][(nt & 1) * 2],
                             b[nt >> 1][(nt & 1) * 2 + 1]);
        }

        // --- in-register scan: argmax column per (mt, rh), one insert ---
#pragma unroll
        for (int mt = 0; mt < 2; mt++)
#pragma unroll
            for (int rh = 0; rh < 2; rh++) {
                float best = acc[mt][0][rh * 2];
                int   bc   = 0;
#pragma unroll
                for (int nt = 0; nt < 4; nt++)
#pragma unroll
                    for (int e2 = 0; e2 < 2; e2++) {
                        float vv = acc[mt][nt][rh * 2 + e2];
                        int   cc = nt * 8 + e2;
                        if (vv > best) { best = vv; bc = cc; }
                    }
                uint32_t pk = (fkey(best) & 0xFFFE0000u) |
                              (colbase + (uint32_t)bc);
                chain4(L[mt][rh], pk);
            }

        if (has_next) {
            char* yd = smem + YS_OFF + (cb ^ 1) * YS_SIZE;
#pragma unroll
            for (int i = 0; i < 8; i++) {
                int fi = t + i * 256;
                int row = fi >> 5, c4 = fi & 31;
                __nv_bfloat162 p0 = __float22bfloat162_rn(make_float2(pf[i].x, pf[i].y));
                __nv_bfloat162 p1 = __float22bfloat162_rn(make_float2(pf[i].z, pf[i].w));
                uint32_t off = (uint32_t)(row * 256) +
                               (((c4 >> 1) ^ (row & 7)) << 4) + ((c4 & 1) << 3);
                *reinterpret_cast<uint2*>(yd + off) =
                    make_uint2(*reinterpret_cast<uint32_t*>(&p0),
                               *reinterpret_cast<uint32_t*>(&p1));
            }
        }
        cb ^= 1;
        __syncthreads();
    }

    // --- butterfly merge across tg, write per (row, sc, ng) top-4 ---
#pragma unroll
    for (int mt = 0; mt < 2; mt++)
#pragma unroll
        for (int rh = 0; rh < 2; rh++) {
            uint32_t* l = L[mt][rh];
#pragma unroll
            for (int xb = 1; xb <= 2; xb <<= 1) {
                uint32_t o0 = __shfl_xor_sync(0xFFFFFFFFu, l[0], xb);
                uint32_t o1 = __shfl_xor_sync(0xFFFFFFFFu, l[1], xb);
                uint32_t o2 = __shfl_xor_sync(0xFFFFFFFFu, l[2], xb);
                uint32_t o3 = __shfl_xor_sync(0xFFFFFFFFu, l[3], xb);
                chain4(l, o0); chain4(l, o1); chain4(l, o2); chain4(l, o3);
            }
            if (tg == 0) {
                int row = half * 128 + wm * 32 + mt * 16 + rh * 8 + g;
                size_t base = (size_t)row * NC + (size_t)(sc * 2 + ng) * 4;
                *reinterpret_cast<uint4*>(&g_cpack[base]) =
                    make_uint4(l[0], l[1], l[2], l[3]);
            }
        }
}

// ---------------------------------------------------------------------------
// Kernel 2: per-row merge -> top-NSEL columns -> 13 exact fp32 dots ->
//           exact top-num_neg -> hinge + masked softmax -> atomicAdd
//   One block per row, 128 threads. ALL shfls run with full warps.
// ---------------------------------------------------------------------------
__global__ __launch_bounds__(128) void merge_loss_kernel(
    const float* __restrict__ X, const float* __restrict__ Y,
    const int* __restrict__ numneg_ptr, float* __restrict__ out,
    int N, int Btot)
{
    const int b = blockIdx.x;
    const int t = threadIdx.x;

    __shared__ float    xrow[DIM];
    __shared__ uint32_t cand[512];
    __shared__ uint32_t wtop[NSEL];
    __shared__ float    ex[NSEL + 1];

    int num_neg = 5;
    if (numneg_ptr) {
        int nn = *numneg_ptr;
        if (nn >= 1 && nn <= KK) num_neg = nn;
    }
    const int pos = g_pos[b];

    xrow[t] = X[(size_t)b * DIM + t];

    // stage 1: 128 threads keep top-4 over strided candidate subset (<=10 each)
    {
        const uint32_t* cp = g_cpack + (size_t)b * NC;
        uint32_t M[4];
#pragma unroll
        for (int j = 0; j < 4; j++) M[j] = 0;
        for (int j = t; j < NC; j += 128) chain4(M, cp[j]);
#pragma unroll
        for (int j = 0; j < 4; j++) cand[t * 4 + j] = M[j];
    }
    __syncthreads();

    // stage 2: warp 0 selects global top-NSEL packed columns (unique keys)
    if (t < 32) {
        uint32_t W[8];
#pragma unroll
        for (int j = 0; j < 8; j++) W[j] = 0;
#pragma unroll
        for (int k = 0; k < 16; k++) chain8(W, cand[t + (k << 5)]);
        int p = 0;
        for (int r = 0; r < NSEL; r++) {
            uint32_t head = (p < 8) ? W[p] : 0u;
            uint32_t w = head;
#pragma unroll
            for (int off = 16; off; off >>= 1) {
                uint32_t o = __shfl_xor_sync(0xFFFFFFFFu, w, off);
                w = (o > w) ? o : w;
            }
            if (head == w && w != 0u && p < 8) p++;
            if (t == 0) wtop[r] = w;
        }
    }
    __syncthreads();

    // rescore: 13 exact dots in 8-thread groups — UNIFORM across all 128
    // threads (gi = 0..15; gi 13..15 compute a dummy dot and discard) so the
    // full-mask shfl is executed by every lane of every warp.
    {
        const int gi = t >> 3, li = t & 7;
        int col = -1;
        if (gi < NSEL) {
            uint32_t w = wtop[gi];
            col = (w > 0x1FFFFu) ? (int)(w & 0x1FFFFu) : -1;
            if (col == pos) col = -1;
        } else if (gi == NSEL) {
            col = pos;
        }
        int safe = (col >= 0 && col < N) ? col : 0;
        const float4* yr = (const float4*)(Y + (size_t)safe * DIM);
        const float4* xr = (const float4*)xrow;
        float s = 0.0f;
#pragma unroll
        for (int j = 0; j < 4; j++) {
            float4 yv = yr[j * 8 + li];
            float4 xv = xr[j * 8 + li];
            s = fmaf(xv.x, yv.x, s);
            s = fmaf(xv.y, yv.y, s);
            s = fmaf(xv.z, yv.z, s);
            s = fmaf(xv.w, yv.w, s);
        }
#pragma unroll
        for (int off = 4; off; off >>= 1)
            s += __shfl_xor_sync(0xFFFFFFFFu, s, off);
        if (li == 0 && gi <= NSEL)
            ex[gi] = (col >= 0 && col < N) ? s : NEGF;
    }
    __syncthreads();

    // final: warp 0 — exact top-num_neg over ex[0..NSEL-1], then epilogue
    if (t < 32) {
        float v   = (t < NSEL) ? ex[t] : NEGF;
        int   idx = t;
        float sim_p = ex[NSEL];
        float stopv[KK];
        for (int r = 0; r < num_neg; r++) {
            float wv = v; int wi = idx;
#pragma unroll
            for (int off = 16; off; off >>= 1) {
                float ov = __shfl_xor_sync(0xFFFFFFFFu, wv, off);
                int   oi = __shfl_xor_sync(0xFFFFFFFFu, wi, off);
                if (ov > wv || (ov == wv && oi < wi)) { wv = ov; wi = oi; }
            }
            if (t == wi) v = NEGF;    // winner drops out
            stopv[r] = wv;
        }
        if (t == 0) {
            float loss[KK], m[KK], mx = NEGF;
            for (int r = 0; r < num_neg; r++) {
                float sn = stopv[r];
                float l = sn - sim_p + 0.3f;
                l = (l > 0.0f) ? l : 0.0f;
                float mm = (l != 0.0f) ? sn : 0.0f;
                loss[r] = l; m[r] = mm;
                if (mm > mx) mx = mm;
            }
            float ssum = 0.0f, res = 0.0f;
            float e[KK];
            for (int r = 0; r < num_neg; r++) { e[r] = expf(m[r] - mx); ssum += e[r]; }
            for (int r = 0; r < num_neg; r++) res += loss[r] * e[r];
            res /= ssum;
            atomicAdd(out, res / ((float)Btot * (float)num_neg));
        }
    }
}

// ---------------------------------------------------------------------------
// kernel_launch
// ---------------------------------------------------------------------------
extern "C" void kernel_launch(void* const* d_in, const int* in_sizes, int n_in,
                              void* d_out, int out_size)
{
    const float* xembs  = (const float*)d_in[0];
    const float* yembs  = (const float*)d_in[1];
    const void*  posind = d_in[3];
    const int*   numneg = (n_in >= 5) ? (const int*)d_in[4] : nullptr;

    const int B = in_sizes[0] / DIM;   // 256
    const int N = in_sizes[1] / DIM;   // 131072
    float* out = (float*)d_out;

    static int smem_set = 0;
    if (!smem_set) {
        cudaFuncSetAttribute(gemm_topk_kernel,
                             cudaFuncAttributeMaxDynamicSharedMemorySize,
                             SMEM_TOTAL);
        smem_set = 1;
    }
    gemm_topk_kernel<<<GRIDX, 256, SMEM_TOTAL>>>(xembs, yembs, posind, out, N, B);
    merge_loss_kernel<<<B, 128>>>(xembs, yembs, numneg, out, N, B);
}

// round 12
// speedup vs baseline: 1.2276x; 1.2276x over previous
#include <cuda_runtime.h>
#include <cuda_bf16.h>
#include <cstdint>

// ---------------------------------------------------------------------------
// Problem constants
// ---------------------------------------------------------------------------
#define DIM   128
#define B_FIX 256
#define N_FIX 131072
#define TN    64                  // y-rows per subtile (split in 2 across CTAs)
#define SUBT  (N_FIX / TN)        // 2048
#define NSC   148                 // subtile streams (one per SM)
#define GRIDX (NSC * 2)           // 296 CTAs: 2 per SM, N-split
#define NC    (NSC * 2 * 4)       // 1184 packed candidates per row
#define NSEL  12                  // columns rescored exactly
#define KK    8
#define NEGF  -3.0e38f

// ---------------------------------------------------------------------------
// Global scratch (static)
// ---------------------------------------------------------------------------
__device__ uint32_t g_cpack[(size_t)B_FIX * NC];   // key15<<17 | column17
__device__ int      g_pos[B_FIX];

// SMEM layout for gemm kernel (bytes)
#define XS_OFF   0
#define XS_SIZE  (256 * 256)                 // 256 rows x 256B (bf16 swizzled)
#define YS_OFF   XS_SIZE                     // 65536
#define YS_SIZE  (32 * 256)                  // 8192 per buffer (32-row half)
#define SMEM_TOTAL (YS_OFF + 2 * YS_SIZE)    // 81920 -> 2 CTAs/SM (160KB/SM)

// ---------------------------------------------------------------------------
// Helpers
// ---------------------------------------------------------------------------
__device__ __forceinline__ uint32_t smem_u32(const void* p) {
    uint32_t a;
    asm("{ .reg .u64 t; cvta.to.shared.u64 t, %1; cvt.u32.u64 %0, t; }"
        : "=r"(a) : "l"(p));
    return a;
}

__device__ __forceinline__ void ldsm_x4(uint32_t* r, uint32_t addr) {
    asm volatile("ldmatrix.sync.aligned.m8n8.x4.shared.b16 {%0,%1,%2,%3}, [%4];"
                 : "=r"(r[0]), "=r"(r[1]), "=r"(r[2]), "=r"(r[3]) : "r"(addr));
}

__device__ __forceinline__ void mma_bf16(float* d, const uint32_t* a,
                                         uint32_t b0, uint32_t b1) {
    asm volatile(
        "mma.sync.aligned.m16n8k16.row.col.f32.bf16.bf16.f32 "
        "{%0,%1,%2,%3}, {%4,%5,%6,%7}, {%8,%9}, {%0,%1,%2,%3};"
        : "+f"(d[0]), "+f"(d[1]), "+f"(d[2]), "+f"(d[3])
        : "r"(a[0]), "r"(a[1]), "r"(a[2]), "r"(a[3]), "r"(b0), "r"(b1));
}

// monotone uint key from float bits (order-preserving, both signs)
__device__ __forceinline__ uint32_t fkey(float v) {
    uint32_t f = __float_as_uint(v);
    return f ^ (uint32_t)(((int32_t)f >> 31) | 0x80000000);
}

// branchless sorted-descending insert chains (IMNMX only)
__device__ __forceinline__ void chain4(uint32_t* L, uint32_t m) {
#pragma unroll
    for (int j = 0; j < 4; j++) {
        uint32_t mx = max(L[j], m);
        m = min(L[j], m);
        L[j] = mx;
    }
}
__device__ __forceinline__ void chain8(uint32_t* L, uint32_t m) {
#pragma unroll
    for (int j = 0; j < 8; j++) {
        uint32_t mx = max(L[j], m);
        m = min(L[j], m);
        L[j] = mx;
    }
}

// ---------------------------------------------------------------------------
// Kernel 1: persistent bf16 mma.sync GEMM + in-register column-argmax mining.
//   296 CTAs x 256 threads, 2/SM (N-split). CTA bx owns ALL 256 x-rows and
//   the 32-col Y half ch = bx&1 of subtile stream sc = bx>>1.
//   8 warps, warp wm owns rows wm*32..wm*32+31 x 32 N-cols.
//   Every Y element is loaded + converted exactly once chip-wide.
// ---------------------------------------------------------------------------
__global__ __launch_bounds__(256, 2)
void gemm_topk_kernel(const float* __restrict__ X, const float* __restrict__ Y,
                      const void* __restrict__ pos_inds, float* __restrict__ outp,
                      int N, int B) {
    extern __shared__ char smem[];
    __shared__ int s_not64;
    const uint32_t sb = smem_u32(smem);
    const int t    = threadIdx.x;
    const int lane = t & 31;
    const int wm   = t >> 5;      // m-group 0..7 (32 rows each)
    const int g    = lane >> 2;   // fragment row-within-8
    const int tg   = lane & 3;    // fragment col-pair
    const int bx   = blockIdx.x;
    const int ch   = bx & 1;      // n-half of each subtile: cols ch*32..ch*32+31
    const int sc   = bx >> 1;     // subtile stream 0..147

    // --- prep (block 0): zero out, sniff pos_inds dtype ---
    if (bx == 0 && t == 0) { outp[0] = 0.0f; s_not64 = 0; }
    __syncthreads();
    if (bx == 0 && t < B / 2) {
        long long v = ((const long long*)pos_inds)[t];
        if (v < 0 || v >= (long long)N) atomicExch(&s_not64, 1);
    }

    // --- load X (256x128 fp32 -> bf16) into swizzled SMEM ---
    {
        const float4* xs = (const float4*)X;
#pragma unroll
        for (int i = 0; i < 32; i++) {
            int fi = t + i * 256;
            int row = fi >> 5, c4 = fi & 31;
            float4 v = xs[fi];
            __nv_bfloat162 p0 = __float22bfloat162_rn(make_float2(v.x, v.y));
            __nv_bfloat162 p1 = __float22bfloat162_rn(make_float2(v.z, v.w));
            uint32_t off = XS_OFF + row * 256 +
                           (((c4 >> 1) ^ (row & 7)) << 4) + ((c4 & 1) << 3);
            *reinterpret_cast<uint2*>(smem + off) =
                make_uint2(*reinterpret_cast<uint32_t*>(&p0),
                           *reinterpret_cast<uint32_t*>(&p1));
        }
    }

    // --- prefetch + store first Y half-subtile (32 rows) into buffer 0 ---
    float4 pf[4];
    {
        const float4* ys = (const float4*)(Y + (size_t)(sc * TN + ch * 32) * DIM);
#pragma unroll
        for (int i = 0; i < 4; i++) pf[i] = ys[t + i * 256];
#pragma unroll
        for (int i = 0; i < 4; i++) {
            int fi = t + i * 256;
            int row = fi >> 5, c4 = fi & 31;
            __nv_bfloat162 p0 = __float22bfloat162_rn(make_float2(pf[i].x, pf[i].y));
            __nv_bfloat162 p1 = __float22bfloat162_rn(make_float2(pf[i].z, pf[i].w));
            uint32_t off = YS_OFF + row * 256 +
                           (((c4 >> 1) ^ (row & 7)) << 4) + ((c4 & 1) << 3);
            *reinterpret_cast<uint2*>(smem + off) =
                make_uint2(*reinterpret_cast<uint32_t*>(&p0),
                           *reinterpret_cast<uint32_t*>(&p1));
        }
    }
    __syncthreads();

    if (bx == 0 && t < B) {
        g_pos[t] = s_not64 ? ((const int*)pos_inds)[t]
                           : (int)((const long long*)pos_inds)[t];
    }

    // --- per-lane candidate lists: 4 rows (mt,rh), top-4 packed keys each ---
    uint32_t L[2][2][4];
#pragma unroll
    for (int mt = 0; mt < 2; mt++)
#pragma unroll
        for (int rh = 0; rh < 2; rh++)
#pragma unroll
            for (int j = 0; j < 4; j++) L[mt][rh][j] = 0;

    const int sub = lane >> 3, lr = lane & 7;
    const uint32_t colbase0 = (uint32_t)(ch * 32 + tg * 2);
    int cb = 0;
    for (int st = sc; st < SUBT; st += NSC) {
        const int stn = st + NSC;
        const bool has_next = (stn < SUBT);

        if (has_next) {
            const float4* ys =
                (const float4*)(Y + (size_t)(stn * TN + ch * 32) * DIM);
#pragma unroll
            for (int i = 0; i < 4; i++) pf[i] = ys[t + i * 256];
        }

        const uint32_t ysb = sb + YS_OFF + cb * YS_SIZE;
        const uint32_t colbase = (uint32_t)(st * 64) + colbase0;

        float acc[2][4][4];
#pragma unroll
        for (int mt = 0; mt < 2; mt++)
#pragma unroll
            for (int nt = 0; nt < 4; nt++)
#pragma unroll
                for (int e = 0; e < 4; e++) acc[mt][nt][e] = 0.0f;

#pragma unroll
        for (int kt = 0; kt < 8; kt++) {
            uint32_t a[2][4], b[2][4];
            {
                int rowa = wm * 32 + ((sub & 1) << 3) + lr;
                int ca   = 2 * kt + (sub >> 1);
#pragma unroll
                for (int mt = 0; mt < 2; mt++) {
                    int row = rowa + mt * 16;
                    uint32_t addr = sb + XS_OFF + row * 256 +
                                    ((ca ^ (row & 7)) << 4);
                    ldsm_x4(a[mt], addr);
                }
            }
            {
                int rowb = ((sub >> 1) << 3) + lr;     // 0..15 within 32-row tile
                int cbk  = 2 * kt + (sub & 1);
#pragma unroll
                for (int p = 0; p < 2; p++) {
                    int row = rowb + p * 16;
                    uint32_t addr = ysb + row * 256 + ((cbk ^ (row & 7)) << 4);
                    ldsm_x4(b[p], addr);
                }
            }
#pragma unroll
            for (int mt = 0; mt < 2; mt++)
#pragma unroll
                for (int nt = 0; nt < 4; nt++)
                    mma_bf16(acc[mt][nt], a[mt],
                             b[nt >> 1][(nt & 1) * 2],
                             b[nt >> 1][(nt & 1) * 2 + 1]);
        }

        // --- in-register scan: argmax column per (mt, rh), one insert ---
#pragma unroll
        for (int mt = 0; mt < 2; mt++)
#pragma unroll
            for (int rh = 0; rh < 2; rh++) {
                float best = acc[mt][0][rh * 2];
                int   bc   = 0;
#pragma unroll
                for (int nt = 0; nt < 4; nt++)
#pragma unroll
                    for (int e2 = 0; e2 < 2; e2++) {
                        float vv = acc[mt][nt][rh * 2 + e2];
                        int   cc = nt * 8 + e2;
                        if (vv > best) { best = vv; bc = cc; }
                    }
                uint32_t pk = (fkey(best) & 0xFFFE0000u) |
                              (colbase + (uint32_t)bc);
                chain4(L[mt][rh], pk);
            }

        if (has_next) {
            char* yd = smem + YS_OFF + (cb ^ 1) * YS_SIZE;
#pragma unroll
            for (int i = 0; i < 4; i++) {
                int fi = t + i * 256;
                int row = fi >> 5, c4 = fi & 31;
                __nv_bfloat162 p0 = __float22bfloat162_rn(make_float2(pf[i].x, pf[i].y));
                __nv_bfloat162 p1 = __float22bfloat162_rn(make_float2(pf[i].z, pf[i].w));
                uint32_t off = (uint32_t)(row * 256) +
                               (((c4 >> 1) ^ (row & 7)) << 4) + ((c4 & 1) << 3);
                *reinterpret_cast<uint2*>(yd + off) =
                    make_uint2(*reinterpret_cast<uint32_t*>(&p0),
                               *reinterpret_cast<uint32_t*>(&p1));
            }
        }
        cb ^= 1;
        __syncthreads();
    }

    // --- butterfly merge across tg, write per (row, sc, ch) top-4 ---
#pragma unroll
    for (int mt = 0; mt < 2; mt++)
#pragma unroll
        for (int rh = 0; rh < 2; rh++) {
            uint32_t* l = L[mt][rh];
#pragma unroll
            for (int xb = 1; xb <= 2; xb <<= 1) {
                uint32_t o0 = __shfl_xor_sync(0xFFFFFFFFu, l[0], xb);
                uint32_t o1 = __shfl_xor_sync(0xFFFFFFFFu, l[1], xb);
                uint32_t o2 = __shfl_xor_sync(0xFFFFFFFFu, l[2], xb);
                uint32_t o3 = __shfl_xor_sync(0xFFFFFFFFu, l[3], xb);
                chain4(l, o0); chain4(l, o1); chain4(l, o2); chain4(l, o3);
            }
            if (tg == 0) {
                int row = wm * 32 + mt * 16 + rh * 8 + g;
                size_t base = (size_t)row * NC + (size_t)(sc * 2 + ch) * 4;
                *reinterpret_cast<uint4*>(&g_cpack[base]) =
                    make_uint4(l[0], l[1], l[2], l[3]);
            }
        }
}

// ---------------------------------------------------------------------------
// Kernel 2: per-row merge -> top-NSEL columns -> 13 exact fp32 dots ->
//           exact top-num_neg -> hinge + masked softmax -> atomicAdd
//   One block per row, 128 threads. ALL shfls run with full warps.
// ---------------------------------------------------------------------------
__global__ __launch_bounds__(128) void merge_loss_kernel(
    const float* __restrict__ X, const float* __restrict__ Y,
    const int* __restrict__ numneg_ptr, float* __restrict__ out,
    int N, int Btot)
{
    const int b = blockIdx.x;
    const int t = threadIdx.x;

    __shared__ float    xrow[DIM];
    __shared__ uint32_t cand[512];
    __shared__ uint32_t wtop[NSEL];
    __shared__ float    ex[NSEL + 1];

    int num_neg = 5;
    if (numneg_ptr) {
        int nn = *numneg_ptr;
        if (nn >= 1 && nn <= KK) num_neg = nn;
    }
    const int pos = g_pos[b];

    xrow[t] = X[(size_t)b * DIM + t];

    // stage 1: 128 threads keep top-4 over strided uint4 candidate loads
    {
        const uint4* cp4 =
            reinterpret_cast<const uint4*>(g_cpack + (size_t)b * NC);
        uint32_t M[4];
#pragma unroll
        for (int j = 0; j < 4; j++) M[j] = 0;
        for (int j = t; j < NC / 4; j += 128) {
            uint4 v = cp4[j];
            chain4(M, v.x); chain4(M, v.y); chain4(M, v.z); chain4(M, v.w);
        }
#pragma unroll
        for (int j = 0; j < 4; j++) cand[t * 4 + j] = M[j];
    }
    __syncthreads();

    // stage 2: warp 0 selects global top-NSEL packed columns (unique keys)
    if (t < 32) {
        uint32_t W[8];
#pragma unroll
        for (int j = 0; j < 8; j++) W[j] = 0;
#pragma unroll
        for (int k = 0; k < 16; k++) chain8(W, cand[t + (k << 5)]);
        int p = 0;
        for (int r = 0; r < NSEL; r++) {
            uint32_t head = (p < 8) ? W[p] : 0u;
            uint32_t w = head;
#pragma unroll
            for (int off = 16; off; off >>= 1) {
                uint32_t o = __shfl_xor_sync(0xFFFFFFFFu, w, off);
                w = (o > w) ? o : w;
            }
            if (head == w && w != 0u && p < 8) p++;
            if (t == 0) wtop[r] = w;
        }
    }
    __syncthreads();

    // rescore: 13 exact dots in 8-thread groups — UNIFORM across all 128
    // threads so the full-mask shfl is executed by every lane of every warp.
    {
        const int gi = t >> 3, li = t & 7;
        int col = -1;
        if (gi < NSEL) {
            uint32_t w = wtop[gi];
            col = (w > 0x1FFFFu) ? (int)(w & 0x1FFFFu) : -1;
            if (col == pos) col = -1;
        } else if (gi == NSEL) {
            col = pos;
        }
        int safe = (col >= 0 && col < N) ? col : 0;
        const float4* yr = (const float4*)(Y + (size_t)safe * DIM);
        const float4* xr = (const float4*)xrow;
        float s = 0.0f;
#pragma unroll
        for (int j = 0; j < 4; j++) {
            float4 yv = yr[j * 8 + li];
            float4 xv = xr[j * 8 + li];
            s = fmaf(xv.x, yv.x, s);
            s = fmaf(xv.y, yv.y, s);
            s = fmaf(xv.z, yv.z, s);
            s = fmaf(xv.w, yv.w, s);
        }
#pragma unroll
        for (int off = 4; off; off >>= 1)
            s += __shfl_xor_sync(0xFFFFFFFFu, s, off);
        if (li == 0 && gi <= NSEL)
            ex[gi] = (col >= 0 && col < N) ? s : NEGF;
    }
    __syncthreads();

    // final: warp 0 — exact top-num_neg over ex[0..NSEL-1], then epilogue
    if (t < 32) {
        float v   = (t < NSEL) ? ex[t] : NEGF;
        int   idx = t;
        float sim_p = ex[NSEL];
        float stopv[KK];
        for (int r = 0; r < num_neg; r++) {
            float wv = v; int wi = idx;
#pragma unroll
            for (int off = 16; off; off >>= 1) {
                float ov = __shfl_xor_sync(0xFFFFFFFFu, wv, off);
                int   oi = __shfl_xor_sync(0xFFFFFFFFu, wi, off);
                if (ov > wv || (ov == wv && oi < wi)) { wv = ov; wi = oi; }
            }
            if (t == wi) v = NEGF;    // winner drops out
            stopv[r] = wv;
        }
        if (t == 0) {
            float loss[KK], m[KK], mx = NEGF;
            for (int r = 0; r < num_neg; r++) {
                float sn = stopv[r];
                float l = sn - sim_p + 0.3f;
                l = (l > 0.0f) ? l : 0.0f;
                float mm = (l != 0.0f) ? sn : 0.0f;
                loss[r] = l; m[r] = mm;
                if (mm > mx) mx = mm;
            }
            float ssum = 0.0f, res = 0.0f;
            float e[KK];
            for (int r = 0; r < num_neg; r++) { e[r] = expf(m[r] - mx); ssum += e[r]; }
            for (int r = 0; r < num_neg; r++) res += loss[r] * e[r];
            res /= ssum;
            atomicAdd(out, res / ((float)Btot * (float)num_neg));
        }
    }
}

// ---------------------------------------------------------------------------
// kernel_launch
// ---------------------------------------------------------------------------
extern "C" void kernel_launch(void* const* d_in, const int* in_sizes, int n_in,
                              void* d_out, int out_size)
{
    const float* xembs  = (const float*)d_in[0];
    const float* yembs  = (const float*)d_in[1];
    const void*  posind = d_in[3];
    const int*   numneg = (n_in >= 5) ? (const int*)d_in[4] : nullptr;

    const int B = in_sizes[0] / DIM;   // 256
    const int N = in_sizes[1] / DIM;   // 131072
    float* out = (float*)d_out;

    static int smem_set = 0;
    if (!smem_set) {
        cudaFuncSetAttribute(gemm_topk_kernel,
                             cudaFuncAttributeMaxDynamicSharedMemorySize,
                             SMEM_TOTAL);
        smem_set = 1;
    }
    gemm_topk_kernel<<<GRIDX, 256, SMEM_TOTAL>>>(xembs, yembs, posind, out, N, B);
    merge_loss_kernel<<<B, 128>>>(xembs, yembs, numneg, out, N, B);
}